// round 11
// baseline (speedup 1.0000x reference)
#include <cuda_runtime.h>
#include <math.h>

// Problem constants (from reference setup_inputs)
#define B 8
#define C 64
#define SPATIAL (48*48*48)        // 110592 floats per (b,c) channel
#define SPATIAL4 (SPATIAL/4)      // 27648 float4 per channel
#define SEGS 4                    // quarter-row segments
#define SEG4 (SPATIAL4/SEGS)      // 6912 float4 per segment
#define NBLK1 (B*C*SEGS)          // 2048 reduction blocks
#define R 8
#define NEG_SLOPE 0.01f

// Scratch (no cudaMalloc allowed)
__device__ float g_partials[NBLK1];
__device__ int   g_idx[B * R];

// ---------------------------------------------------------------------------
// Kernel 1: quarter-row partial sums. 2048 blocks x 256 threads.
// PDL trigger after each block publishes its partial.
// ---------------------------------------------------------------------------
__global__ __launch_bounds__(256) void mean_partial_kernel(
    const float* __restrict__ x, float* __restrict__ partials) {
    const int blk = blockIdx.x;          // row*4 + seg
    const int row = blk >> 2;
    const int seg = blk & 3;
    const float4* __restrict__ p =
        reinterpret_cast<const float4*>(x + (size_t)row * SPATIAL) + seg * SEG4;

    float ax = 0.f, ay = 0.f, az = 0.f, aw = 0.f;
    // 6912 / 256 = 27 iterations
#pragma unroll 9
    for (int i = threadIdx.x; i < SEG4; i += 256) {
        float4 v = p[i];
        ax += v.x; ay += v.y; az += v.z; aw += v.w;
    }
    float acc = (ax + ay) + (az + aw);

    for (int off = 16; off > 0; off >>= 1)
        acc += __shfl_down_sync(0xFFFFFFFFu, acc, off);

    __shared__ float warp_sums[8];
    const int lane = threadIdx.x & 31;
    const int wid  = threadIdx.x >> 5;
    if (lane == 0) warp_sums[wid] = acc;
    __syncthreads();

    if (threadIdx.x == 0) {
        float s = warp_sums[0] + warp_sums[1] + warp_sums[2] + warp_sums[3]
                + warp_sums[4] + warp_sums[5] + warp_sums[6] + warp_sums[7];
        partials[blk] = s;
        cudaTriggerProgrammaticLaunchCompletion();
    }
}

// ---------------------------------------------------------------------------
// Kernel 2 (PDL secondary): 64 blocks, block j handles (b = j>>3, r = j&7).
// Pre-sync: stage weights/biases in smem (overlaps kernel-1 tail).
// Post-sync: warp-cooperative MLP + rank-based pick -> g_idx[j].
// rank(j') = #{channels beating j'} with smaller-index tie-break == the
// order of repeated strict-argmax == jax.lax.top_k order.
// ---------------------------------------------------------------------------
__global__ __launch_bounds__(256) void idx_kernel(
    const float* __restrict__ w1, const float* __restrict__ b1,
    const float* __restrict__ w2, const float* __restrict__ b2,
    const float* __restrict__ partials,
    int* __restrict__ idx_out) {

    __shared__ float sw1[C * C];     // 16 KB
    __shared__ float sw2[C * C];     // 16 KB
    __shared__ float sb1[C], sb2[C];
    __shared__ float mb[C];
    __shared__ float y1s[C];
    __shared__ float zs[C];

    const int j = blockIdx.x;        // 0..63 : b*R + r
    const int b = j >> 3;
    const int r = j & 7;
    const int t = threadIdx.x;
    const int lane = t & 31;
    const int wrp  = t >> 5;         // 0..7

    // ---- Pre-sync staging --------------------------------------------------
#pragma unroll
    for (int k = 0; k < 16; k++) {
        sw1[t + k * 256] = w1[t + k * 256];
        sw2[t + k * 256] = w2[t + k * 256];
    }
    if (t < C) { sb1[t] = b1[t]; sb2[t] = b2[t]; }

    cudaGridDependencySynchronize();

    if (t < C) {
        float4 ps = reinterpret_cast<const float4*>(partials)[b * C + t];
        mb[t] = ((ps.x + ps.y) + (ps.z + ps.w)) * (1.0f / (float)SPATIAL);
    }
    __syncthreads();

    // layer 1: warp w -> channels 8w..8w+7 (smem weights + shuffle reduce)
    {
        const float m0 = mb[lane];
        const float m1 = mb[lane + 32];
#pragma unroll
        for (int c = 0; c < 8; c++) {
            const int i = 8 * wrp + c;
            float a = m0 * sw1[i * C + lane] + m1 * sw1[i * C + 32 + lane];
#pragma unroll
            for (int off = 16; off > 0; off >>= 1)
                a += __shfl_down_sync(0xFFFFFFFFu, a, off);
            if (lane == 0) {
                a += sb1[i];
                y1s[i] = (a > 0.0f) ? a : NEG_SLOPE * a;
            }
        }
    }
    __syncthreads();

    // layer 2: same with w2, sigmoid
    {
        const float h0 = y1s[lane];
        const float h1 = y1s[lane + 32];
#pragma unroll
        for (int c = 0; c < 8; c++) {
            const int i = 8 * wrp + c;
            float a = h0 * sw2[i * C + lane] + h1 * sw2[i * C + 32 + lane];
#pragma unroll
            for (int off = 16; off > 0; off >>= 1)
                a += __shfl_down_sync(0xFFFFFFFFu, a, off);
            if (lane == 0) {
                a += sb2[i];
                zs[i] = 1.0f / (1.0f + expf(-a));
            }
        }
    }
    __syncthreads();

    // rank-based selection: write the channel whose rank == r.
    if (t < C) {
        const float z = zs[t];
        int rank = 0;
#pragma unroll
        for (int jj = 0; jj < C; jj++) {
            const float v = zs[jj];
            rank += (v > z) || (v == z && jj < t);
        }
        if (rank == r) {
            idx_out[j] = t;
            __threadfence();
        }
    }
    __syncthreads();
    if (t == 0) cudaTriggerProgrammaticLaunchCompletion();
}

// ---------------------------------------------------------------------------
// Kernel 3 (PDL secondary of kernel 2): pure gather, measured-best config.
// grid = (27, 64), 256 threads, 4 float4/thread.
// ---------------------------------------------------------------------------
__global__ __launch_bounds__(256) void gather_kernel(const float* __restrict__ x,
                                                     const int* __restrict__ idx,
                                                     float* __restrict__ out) {
    cudaGridDependencySynchronize();

    const int row = blockIdx.y;          // 0..63 : b*R + r
    const int b   = row >> 3;
    const int ch  = __ldg(idx + row);

    const float4* __restrict__ src =
        reinterpret_cast<const float4*>(x + ((size_t)b * C + ch) * SPATIAL);
    float4* __restrict__ dst =
        reinterpret_cast<float4*>(out) + (size_t)row * SPATIAL4;

    const int base = blockIdx.x * (256 * 4) + threadIdx.x;
#pragma unroll
    for (int kk = 0; kk < 4; kk++) {
        const int i = base + kk * 256;
        dst[i] = src[i];   // 27648 = 27*256*4 exactly: no bounds check
    }
}

// ---------------------------------------------------------------------------
extern "C" void kernel_launch(void* const* d_in, const int* in_sizes, int n_in,
                              void* d_out, int out_size) {
    const float* x  = (const float*)d_in[0];
    const float* w1 = (const float*)d_in[1];
    const float* b1 = (const float*)d_in[2];
    const float* w2 = (const float*)d_in[3];
    const float* b2 = (const float*)d_in[4];
    float* out = (float*)d_out;

    float* partials;
    int* idx;
    cudaGetSymbolAddress((void**)&partials, g_partials);
    cudaGetSymbolAddress((void**)&idx, g_idx);

    mean_partial_kernel<<<NBLK1, 256>>>(x, partials);

    cudaLaunchAttribute attrs[1];
    attrs[0].id = cudaLaunchAttributeProgrammaticStreamSerialization;
    attrs[0].val.programmaticStreamSerializationAllowed = 1;

    cudaLaunchConfig_t cfg1 = {};
    cfg1.gridDim  = dim3(B * R, 1, 1);    // 64 blocks
    cfg1.blockDim = dim3(256, 1, 1);
    cfg1.attrs = attrs;
    cfg1.numAttrs = 1;
    cudaLaunchKernelEx(&cfg1, idx_kernel, w1, b1, w2, b2,
                       (const float*)partials, idx);

    cudaLaunchConfig_t cfg2 = {};
    cfg2.gridDim  = dim3(27, B * R, 1);   // (27, 64)
    cfg2.blockDim = dim3(256, 1, 1);
    cfg2.attrs = attrs;
    cfg2.numAttrs = 1;
    cudaLaunchKernelEx(&cfg2, gather_kernel, x, (const int*)idx, out);
}